// round 9
// baseline (speedup 1.0000x reference)
#include <cuda_runtime.h>
#include <cuda_fp16.h>
#include <cstdint>

#define NROWS 65536
#define D 128
#define TMAX 2048

// smem: rp 2KB | bias 2KB | 3 stages x (A 8KB + W 64KB); epilogue Gbuf overlays stages
#define A_OFF   4096
#define STAGE   73728
#define SMEM_SZ (4096 + 3 * 73728)

// ---------------- scratch ----------------
__device__ __half g_mem16[2][(size_t)NROWS * D];
__device__ __half g_feat16[2][(size_t)NROWS * D];
__device__ __half g_TEtab16[2 * TMAX * D];
__device__ __half g_Wc[2][(size_t)512 * 640];     // combined [n=512][k=640]
__device__ int g_hidx[NROWS], g_gidx[NROWS], g_trel[NROWS], g_fidx1[NROWS], g_pick[NROWS];

// ---------------- ptx helpers ----------------
__device__ __forceinline__ void mma_f16(float* c, const uint32_t* a, uint32_t b0, uint32_t b1) {
    asm volatile(
        "mma.sync.aligned.m16n8k16.row.col.f32.f16.f16.f32 "
        "{%0,%1,%2,%3}, {%4,%5,%6,%7}, {%8,%9}, {%0,%1,%2,%3};\n"
        : "+f"(c[0]), "+f"(c[1]), "+f"(c[2]), "+f"(c[3])
        : "r"(a[0]), "r"(a[1]), "r"(a[2]), "r"(a[3]), "r"(b0), "r"(b1));
}
__device__ __forceinline__ void cp16(uint32_t dst, const void* src) {
    asm volatile("cp.async.cg.shared.global [%0], [%1], 16;\n" :: "r"(dst), "l"(src));
}
__device__ __forceinline__ void ldsm4(uint32_t* r, uint32_t addr) {
    asm volatile("ldmatrix.sync.aligned.m8n8.x4.shared.b16 {%0,%1,%2,%3}, [%4];"
                 : "=r"(r[0]), "=r"(r[1]), "=r"(r[2]), "=r"(r[3]) : "r"(addr));
}

// ---------------- one-time conversion kernels ----------------
__global__ void te_table16_kernel(const float* __restrict__ wm, const float* __restrict__ bm,
                                  const float* __restrict__ wp, const float* __restrict__ bp)
{
    int t = blockIdx.x, k = threadIdx.x;
    float tf = (float)t;
    g_TEtab16[t * D + k]            = __float2half_rn(cosf(tf * wm[k] + bm[k]));
    g_TEtab16[TMAX * D + t * D + k] = __float2half_rn(cosf(tf * wp[k] + bp[k]));
}

// combined weight W'[n=512][k=640]: x-part k<512 = [Wr|Wz|Wn|0], h-part = [Ur|Uz|0|Un]
__global__ void wc_kernel(const float* __restrict__ Wih0, const float* __restrict__ Whh0,
                          const float* __restrict__ Wih1, const float* __restrict__ Whh1)
{
    int br = blockIdx.y;
    int n  = blockIdx.x;           // 0..511
    int k  = threadIdx.x;          // 0..639
    const float* Wih = br ? Wih1 : Wih0;
    const float* Whh = br ? Whh1 : Whh0;
    float v;
    if (k < 512) v = (n < 384) ? Wih[n * 512 + k] : 0.f;
    else {
        int kk = k - 512;
        v = (n < 256) ? Whh[n * 128 + kk] : ((n >= 384) ? Whh[(n - 128) * 128 + kk] : 0.f);
    }
    g_Wc[br][(size_t)n * 640 + k] = __float2half_rn(v);
}

__global__ void conv_mem_kernel(const float* __restrict__ m0, const float* __restrict__ m1)
{
    int arr = blockIdx.y;
    const float* s = arr ? m1 : m0;
    __half* d = g_mem16[arr];
    size_t i = ((size_t)blockIdx.x * 256 + threadIdx.x) * 4;
    float4 v = *(const float4*)(s + i);
    *(__half2*)(d + i)     = __floats2half2_rn(v.x, v.y);
    *(__half2*)(d + i + 2) = __floats2half2_rn(v.z, v.w);
}

// ---------------- descriptors + last_up ----------------
__global__ void prep_kernel(const int* __restrict__ n_id,
                            const int* __restrict__ other_s, const int* __restrict__ other_d,
                            const int* __restrict__ t_s, const int* __restrict__ t_d,
                            const int* __restrict__ last_update,
                            float* __restrict__ out)
{
    int row = blockIdx.x * 256 + threadIdx.x;
    if (row >= NROWS) return;
    int ts = t_s[row], td = t_d[row];
    bool pick = (ts >= td);
    int nid = n_id[row];
    int tpick = pick ? ts : td;
    g_hidx[row]  = nid;
    g_gidx[row]  = pick ? other_s[row] : other_d[row];
    g_trel[row]  = tpick - last_update[nid];
    g_pick[row]  = pick ? 1 : 0;
    g_fidx1[row] = pick ? nid : other_d[row];
    out[(size_t)2 * NROWS * D + row] = (float)tpick;
}

// ---------------- feature pick/gather + convert ----------------
__global__ void feat_kernel(const float* __restrict__ msg_s, const float* __restrict__ msg_d,
                            const float* __restrict__ pos_emb)
{
    int warp = threadIdx.x >> 5, lane = threadIdx.x & 31;
    int row = blockIdx.x * 4 + (warp >> 1);
    int br  = warp & 1;
    const float* src = br ? pos_emb + (size_t)g_fidx1[row] * D
                          : (g_pick[row] ? msg_s : msg_d) + (size_t)row * D;
    float4 v = *(const float4*)(src + lane * 4);
    __half* d = g_feat16[br] + (size_t)row * D + lane * 4;
    *(__half2*)d       = __floats2half2_rn(v.x, v.y);
    *(__half2*)(d + 2) = __floats2half2_rn(v.z, v.w);
}

// ---------------- fused GEMM+GRU: BM=64, BN=512, BK=64, 512 thr, warp grid 2m x 8n ----------------
// grid (1024 row-blocks, 2 branches); 10 K-slabs; epilogue recombines gates in smem.
__global__ void __launch_bounds__(512, 1)
gemm_fused(const float* __restrict__ memory, const float* __restrict__ pos_mem,
           const float* __restrict__ bih0, const float* __restrict__ bhh0,
           const float* __restrict__ bih1, const float* __restrict__ bhh1,
           float* __restrict__ out)
{
    extern __shared__ char sm[];
    const __half** rp = (const __half**)sm;          // 4 chunks x 64 row pointers
    float* sbias = (float*)(sm + 2048);              // 512 floats
    uint32_t su = (uint32_t)__cvta_generic_to_shared(sm);

    int br = blockIdx.y, rb = blockIdx.x;
    int tid = threadIdx.x, lane = tid & 31, warp = tid >> 5;
    int wm = warp & 1, wn = warp >> 1;

    if (tid < 64) {
        int R = rb * 64 + tid;
        rp[tid]       = g_mem16[br] + (size_t)g_hidx[R] * D;
        rp[64 + tid]  = g_mem16[br] + (size_t)g_gidx[R] * D;
        rp[128 + tid] = g_feat16[br] + (size_t)R * D;
        rp[192 + tid] = g_TEtab16 + (size_t)br * TMAX * D + (size_t)g_trel[R] * D;
    }
    if (tid < 128) {
        const float* bih = br ? bih1 : bih0;
        const float* bhh = br ? bhh1 : bhh0;
        sbias[tid]       = bih[tid]       + bhh[tid];
        sbias[128 + tid] = bih[128 + tid] + bhh[128 + tid];
        sbias[256 + tid] = bih[256 + tid];
        sbias[384 + tid] = bhh[256 + tid];
    }
    __syncthreads();

    const char* WcB = (const char*)g_Wc[br];
    int arow = tid >> 3, j = tid & 7;

    auto issue = [&](int s) {
        if (s < 10) {
            uint32_t base = su + A_OFF + (s % 3) * STAGE;
            int c    = (s < 8) ? (s >> 1) : 0;
            int koff = (s < 8) ? (s & 1) * 128 : (s - 8) * 128;      // bytes within row
            cp16(base + arow * 128 + ((j ^ (arow & 7)) << 4),
                 (const char*)rp[c * 64 + arow] + koff + j * 16);
            uint32_t wb = base + 8192;
            #pragma unroll
            for (int p = 0; p < 8; ++p) {
                int wrow = arow + p * 64;
                cp16(wb + wrow * 128 + ((j ^ (wrow & 7)) << 4),
                     WcB + (size_t)wrow * 1280 + s * 128 + j * 16);
            }
        }
        asm volatile("cp.async.commit_group;\n");
    };

    // fragment lane constants
    int x7 = lane & 7;
    int a_kh = lane >> 4;
    int b_kh = (lane >> 3) & 1;
    uint32_t aRowOff = (uint32_t)((wm * 32 + ((lane >> 3) & 1) * 8 + (lane & 7)) * 128);
    uint32_t bRowOff = (uint32_t)((wn * 64 + (lane >> 4) * 8 + (lane & 7)) * 128);

    float acc[2][8][4];
    #pragma unroll
    for (int i = 0; i < 2; ++i)
        #pragma unroll
        for (int n = 0; n < 8; ++n)
            #pragma unroll
            for (int q = 0; q < 4; ++q) acc[i][n][q] = 0.f;

    issue(0);
    issue(1);

    for (int s = 0; s < 10; ++s) {
        asm volatile("cp.async.wait_group 1;\n");
        __syncthreads();
        issue(s + 2);

        uint32_t aSt = su + A_OFF + (s % 3) * STAGE;
        uint32_t wSt = aSt + 8192;
        #pragma unroll
        for (int s2 = 0; s2 < 4; ++s2) {
            uint32_t aj = (uint32_t)(((s2 * 2 + a_kh) ^ x7) << 4);
            uint32_t bj = (uint32_t)(((s2 * 2 + b_kh) ^ x7) << 4);
            uint32_t Af[2][4];
            #pragma unroll
            for (int mf = 0; mf < 2; ++mf)
                ldsm4(Af[mf], aSt + aRowOff + mf * 2048 + aj);
            uint32_t Bf[4][4];
            #pragma unroll
            for (int p = 0; p < 4; ++p)
                ldsm4(Bf[p], wSt + bRowOff + p * 2048 + bj);
            #pragma unroll
            for (int nf = 0; nf < 8; ++nf) {
                uint32_t b0 = Bf[nf >> 1][(nf & 1) * 2];
                uint32_t b1 = Bf[nf >> 1][(nf & 1) * 2 + 1];
                #pragma unroll
                for (int mf = 0; mf < 2; ++mf)
                    mma_f16(&acc[mf][nf][0], Af[mf], b0, b1);
            }
        }
    }

    // ---------------- epilogue: gates -> smem (stride 516, conflict-free) -> GRU -> out ----------------
    asm volatile("cp.async.wait_group 0;\n");
    __syncthreads();
    float* Gb = (float*)(sm + A_OFF);
    #pragma unroll
    for (int mf = 0; mf < 2; ++mf) {
        int r = wm * 32 + mf * 16 + (lane >> 2);
        #pragma unroll
        for (int nf = 0; nf < 8; ++nf) {
            int col = wn * 64 + nf * 8 + (lane & 3) * 2;
            *(float2*)&Gb[r * 516 + col]       = make_float2(acc[mf][nf][0], acc[mf][nf][1]);
            *(float2*)&Gb[(r + 8) * 516 + col] = make_float2(acc[mf][nf][2], acc[mf][nf][3]);
        }
    }
    __syncthreads();

    {
        int row = tid >> 3;
        int R   = rb * 64 + row;
        int c0  = (tid & 7) * 16;
        const float* mem  = br ? pos_mem : memory;
        const float* hrow = mem + (size_t)g_hidx[R] * D;
        float* op = out + ((size_t)br * NROWS + R) * D;
        const float* gr = &Gb[row * 516];
        #pragma unroll
        for (int q = 0; q < 4; ++q) {
            int jb = c0 + q * 4;
            float4 hv = *(const float4*)&hrow[jb];
            const float* hp = &hv.x;
            float o[4];
            #pragma unroll
            for (int e = 0; e < 4; ++e) {
                int jj = jb + e;
                float r = 1.f / (1.f + expf(-(gr[jj]       + sbias[jj])));
                float z = 1.f / (1.f + expf(-(gr[128 + jj] + sbias[128 + jj])));
                float n = tanhf(gr[256 + jj] + sbias[256 + jj] + r * (gr[384 + jj] + sbias[384 + jj]));
                o[e] = (1.f - z) * n + z * hp[e];
            }
            *(float4*)&op[jb] = make_float4(o[0], o[1], o[2], o[3]);
        }
    }
}

// ---------------- launch ----------------
extern "C" void kernel_launch(void* const* d_in, const int* in_sizes, int n_in,
                              void* d_out, int out_size)
{
    const int*   n_id        = (const int*)  d_in[0];
    const float* memory      = (const float*)d_in[1];
    const float* pos_mem     = (const float*)d_in[2];
    const float* pos_emb     = (const float*)d_in[3];
    const float* raw_msg_s   = (const float*)d_in[4];
    const float* raw_msg_d   = (const float*)d_in[5];
    const int*   other_s     = (const int*)  d_in[6];
    const int*   other_d     = (const int*)  d_in[7];
    const int*   t_s         = (const int*)  d_in[8];
    const int*   t_d         = (const int*)  d_in[9];
    const int*   last_update = (const int*)  d_in[10];
    const float* w_time_mem  = (const float*)d_in[11];
    const float* b_time_mem  = (const float*)d_in[12];
    const float* w_time_pos  = (const float*)d_in[13];
    const float* b_time_pos  = (const float*)d_in[14];
    const float* Wih_mem     = (const float*)d_in[15];
    const float* Whh_mem     = (const float*)d_in[16];
    const float* bih_mem     = (const float*)d_in[17];
    const float* bhh_mem     = (const float*)d_in[18];
    const float* Wih_pos     = (const float*)d_in[19];
    const float* Whh_pos     = (const float*)d_in[20];
    const float* bih_pos     = (const float*)d_in[21];
    const float* bhh_pos     = (const float*)d_in[22];
    float* out = (float*)d_out;

    cudaFuncSetAttribute(gemm_fused, cudaFuncAttributeMaxDynamicSharedMemorySize, SMEM_SZ);

    te_table16_kernel<<<TMAX, 128>>>(w_time_mem, b_time_mem, w_time_pos, b_time_pos);
    wc_kernel<<<dim3(512, 2), 640>>>(Wih_mem, Whh_mem, Wih_pos, Whh_pos);
    conv_mem_kernel<<<dim3(NROWS * D / (256 * 4), 2), 256>>>(memory, pos_mem);
    prep_kernel<<<NROWS / 256, 256>>>(n_id, other_s, other_d, t_s, t_d, last_update, out);
    feat_kernel<<<NROWS / 4, 256>>>(raw_msg_s, raw_msg_d, pos_emb);

    gemm_fused<<<dim3(NROWS / 64, 2), 512, SMEM_SZ>>>(
        memory, pos_mem, bih_mem, bhh_mem, bih_pos, bhh_pos, out);
}